// round 1
// baseline (speedup 1.0000x reference)
#include <cuda_runtime.h>
#include <math.h>

// ---------------------------------------------------------------------------
// GRU: S=1024, B=64, I=512, H=512, fp32
// Phase 1: pregemm  -> g_xg[s][gate][hc][b] = x[s,b,:] . W_g[hc,:] + b_g[hc]
// Phase 2: persistent recurrence kernel, 128 CTAs, custom grid barrier.
// ---------------------------------------------------------------------------

#define S_LEN 1024
#define B_DIM 64
#define I_DIM 512
#define H_DIM 512
#define NB_REC 128          // recurrence grid size (must be <= #SMs)

// scratch: (S, 3, H, B) fp32 = 402 MB
__device__ float g_xg[(size_t)S_LEN * 3 * H_DIM * B_DIM];
// r*h exchange buffer, (B,H) row-major
__device__ float g_rh[B_DIM * H_DIM];
// grid barrier state
__device__ unsigned g_cnt = 0;
__device__ unsigned g_gen = 0;

// ---------------------------------------------------------------------------
// Phase 1: SGEMM  C[m][n] = sum_k A[m][k]*W[n][k] + bias[n]
//   A = x, M = 65536 (m = s*64+b), N = 1536 (n = g*512+hc), K = 512
//   BM=128, BN=128, BK=8, 256 threads, 8x8 thread tile.
//   Store layout: g_xg[((s*3+g)*512+hc)*64 + b]  (coalesced over b)
// ---------------------------------------------------------------------------
__global__ __launch_bounds__(256) void pregemm_kernel(
    const float* __restrict__ x,
    const float* __restrict__ Wz, const float* __restrict__ Wzb,
    const float* __restrict__ Wr, const float* __restrict__ Wrb,
    const float* __restrict__ Wh, const float* __restrict__ Whb)
{
    __shared__ float As[8][132];
    __shared__ float Bs[8][132];

    const int tid = threadIdx.x;
    const int m0 = blockIdx.x * 128;
    const int n0 = blockIdx.y * 128;
    const int g  = n0 >> 9;          // gate (tile never crosses gate boundary)
    const int r0 = n0 & 511;         // row offset within gate weight matrix

    const float* W  = (g == 0) ? Wz  : (g == 1) ? Wr  : Wh;
    const float* Wb = (g == 0) ? Wzb : (g == 1) ? Wrb : Whb;

    // global load indices: 128 rows x 8 k per tile, float4 per thread
    const int lm  = tid >> 1;        // 0..127
    const int lk4 = (tid & 1) << 2;  // 0 or 4
    const float* Aptr = x + (size_t)(m0 + lm) * I_DIM + lk4;
    const float* Bptr = W + (size_t)(r0 + lm) * I_DIM + lk4;

    const int tm = tid & 15;         // m-direction (lanes over m -> coalesced C)
    const int tn = tid >> 4;         // n-direction

    float acc[8][8];
    #pragma unroll
    for (int i = 0; i < 8; i++)
        #pragma unroll
        for (int j = 0; j < 8; j++) acc[i][j] = 0.0f;

    for (int k0 = 0; k0 < I_DIM; k0 += 8) {
        float4 av = *(const float4*)(Aptr + k0);
        float4 bv = *(const float4*)(Bptr + k0);
        __syncthreads();
        As[lk4 + 0][lm] = av.x; As[lk4 + 1][lm] = av.y;
        As[lk4 + 2][lm] = av.z; As[lk4 + 3][lm] = av.w;
        Bs[lk4 + 0][lm] = bv.x; Bs[lk4 + 1][lm] = bv.y;
        Bs[lk4 + 2][lm] = bv.z; Bs[lk4 + 3][lm] = bv.w;
        __syncthreads();
        #pragma unroll
        for (int k = 0; k < 8; k++) {
            float a[8], bb[8];
            *(float4*)(a)     = *(const float4*)(&As[k][tm * 8]);
            *(float4*)(a + 4) = *(const float4*)(&As[k][tm * 8 + 4]);
            *(float4*)(bb)     = *(const float4*)(&Bs[k][tn * 8]);
            *(float4*)(bb + 4) = *(const float4*)(&Bs[k][tn * 8 + 4]);
            #pragma unroll
            for (int i = 0; i < 8; i++)
                #pragma unroll
                for (int j = 0; j < 8; j++)
                    acc[i][j] = fmaf(a[i], bb[j], acc[i][j]);
        }
    }

    // epilogue: bias + store to (S,3,H,B), coalesced float4 over b
    const int gm = m0 + tm * 8;      // 8 consecutive m: same s, b..b+7
    const int s  = gm >> 6;
    const int b  = gm & 63;
    #pragma unroll
    for (int j = 0; j < 8; j++) {
        const int n = n0 + tn * 8 + j;            // global n = g*512 + hc
        const float bias = Wb[r0 + tn * 8 + j];
        float* op = g_xg + (size_t)s * (3 * H_DIM * B_DIM) + (size_t)n * B_DIM + b;
        float4 v0 = make_float4(acc[0][j] + bias, acc[1][j] + bias,
                                acc[2][j] + bias, acc[3][j] + bias);
        float4 v1 = make_float4(acc[4][j] + bias, acc[5][j] + bias,
                                acc[6][j] + bias, acc[7][j] + bias);
        *(float4*)(op)     = v0;
        *(float4*)(op + 4) = v1;
    }
}

// ---------------------------------------------------------------------------
// grid-wide barrier (all NB_REC CTAs co-resident)
// ---------------------------------------------------------------------------
__device__ __forceinline__ void grid_sync()
{
    __threadfence();
    __syncthreads();
    if (threadIdx.x == 0) {
        volatile unsigned* genp = &g_gen;
        unsigned gen = *genp;
        __threadfence();
        unsigned arrived = atomicAdd(&g_cnt, 1u);
        if (arrived == NB_REC - 1u) {
            atomicExch(&g_cnt, 0u);
            __threadfence();
            atomicAdd(&g_gen, 1u);
        } else {
            while (*genp == gen) { __nanosleep(32); }
        }
    }
    __syncthreads();
    __threadfence();
}

// ---------------------------------------------------------------------------
// Phase 2: persistent recurrence.
//   128 CTAs x 256 threads. CTA bx owns hcols [bx*4, bx*4+4).
//   thread: b = tid&63, hcl = tid>>6  -> one (b,hc) element per gate.
//   smem: Uz/Ur/Uh rows (persistent, 24KB) + h/rh stage [64][516] (129KB)
//         + hout[64][4] (1KB)
// ---------------------------------------------------------------------------
#define HS_PITCH 516   // 512 + 4 pad -> conflict-free LDS.128 with lanes over b

__global__ __launch_bounds__(256) void gru_rec_kernel(
    const float* __restrict__ h0,
    const float* __restrict__ Uz, const float* __restrict__ Uzb,
    const float* __restrict__ Ur, const float* __restrict__ Urb,
    const float* __restrict__ Uh, const float* __restrict__ Uhb,
    float* __restrict__ out)
{
    extern __shared__ float sm[];
    float* Uzs  = sm;                        // [4][512]
    float* Urs  = sm + 2048;                 // [4][512]
    float* Uhs  = sm + 4096;                 // [4][512]
    float* hs   = sm + 6144;                 // [64][516]
    float* hout = sm + 6144 + 64 * HS_PITCH; // [64][4]

    const int tid = threadIdx.x;
    const int b   = tid & 63;
    const int hcl = tid >> 6;                        // 0..3
    const int hc  = blockIdx.x * 4 + hcl;            // global h column

    // load this CTA's U rows into smem (persistent across all steps)
    for (int i = tid; i < 4 * 512; i += 256) {
        const int r = i >> 9, c = i & 511;
        const size_t widx = (size_t)(blockIdx.x * 4 + r) * H_DIM + c;
        Uzs[i] = Uz[widx];
        Urs[i] = Ur[widx];
        Uhs[i] = Uh[widx];
    }
    const float bzv = Uzb[hc];
    const float brv = Urb[hc];
    const float bhv = Uhb[hc];

    const float* hprev = h0;   // (B,H) row-major
    float hnew = 0.0f;

    for (int t = 0; t < S_LEN; t++) {
        // ---- stage h_prev into smem (coalesced float4) ----
        __syncthreads();
        for (int i = tid; i < 64 * 128; i += 256) {
            const int bb = i >> 7, k4 = i & 127;
            *(float4*)(hs + bb * HS_PITCH + k4 * 4) =
                *(const float4*)(hprev + bb * H_DIM + k4 * 4);
        }
        __syncthreads();

        // ---- phase 1: z and r gates ----
        const size_t xbase = (size_t)t * (3 * H_DIM * B_DIM) + (size_t)hc * B_DIM + b;
        float az = bzv + g_xg[xbase];
        float ar = brv + g_xg[xbase + (size_t)H_DIM * B_DIM];
        {
            const float* hrow = hs + b * HS_PITCH;
            const float* uzr  = Uzs + hcl * 512;
            const float* urr  = Urs + hcl * 512;
            #pragma unroll 4
            for (int k4 = 0; k4 < 128; k4++) {
                float4 hv = *(const float4*)(hrow + k4 * 4);
                float4 uz = *(const float4*)(uzr + k4 * 4);
                float4 ur = *(const float4*)(urr + k4 * 4);
                az = fmaf(hv.x, uz.x, az); az = fmaf(hv.y, uz.y, az);
                az = fmaf(hv.z, uz.z, az); az = fmaf(hv.w, uz.w, az);
                ar = fmaf(hv.x, ur.x, ar); ar = fmaf(hv.y, ur.y, ar);
                ar = fmaf(hv.z, ur.z, ar); ar = fmaf(hv.w, ur.w, ar);
            }
        }
        const float z = 1.0f / (1.0f + __expf(-az));
        const float r = 1.0f / (1.0f + __expf(-ar));
        const float hown = hs[b * HS_PITCH + hc];

        g_rh[b * H_DIM + hc] = r * hown;

        grid_sync();   // all r*h written globally

        // ---- stage r*h into smem ----
        for (int i = tid; i < 64 * 128; i += 256) {
            const int bb = i >> 7, k4 = i & 127;
            *(float4*)(hs + bb * HS_PITCH + k4 * 4) =
                *(const float4*)(g_rh + bb * H_DIM + k4 * 4);
        }
        __syncthreads();

        // ---- phase 2: candidate + blend ----
        float ah = bhv + g_xg[xbase + (size_t)2 * H_DIM * B_DIM];
        {
            const float* rrow = hs + b * HS_PITCH;
            const float* uhr  = Uhs + hcl * 512;
            #pragma unroll 4
            for (int k4 = 0; k4 < 128; k4++) {
                float4 rv = *(const float4*)(rrow + k4 * 4);
                float4 uh = *(const float4*)(uhr + k4 * 4);
                ah = fmaf(rv.x, uh.x, ah); ah = fmaf(rv.y, uh.y, ah);
                ah = fmaf(rv.z, uh.z, ah); ah = fmaf(rv.w, uh.w, ah);
            }
        }
        const float htld = tanhf(ah);
        hnew = (1.0f - z) * hown + z * htld;

        hout[b * 4 + hcl] = hnew;
        __syncthreads();

        // coalesced-ish write of this CTA's 4 columns for all 64 b
        if (tid < 64) {
            float4 v = *(const float4*)(hout + tid * 4);
            *(float4*)(out + (size_t)t * (B_DIM * H_DIM) + tid * H_DIM + blockIdx.x * 4) = v;
        }

        grid_sync();   // h_t fully written -> next step may stage it
        hprev = out + (size_t)t * (B_DIM * H_DIM);
    }

    // hx = h_{S-1}
    if (tid < 64) {
        float4 v = *(const float4*)(hout + tid * 4);
        *(float4*)(out + (size_t)S_LEN * (B_DIM * H_DIM) + tid * H_DIM + blockIdx.x * 4) = v;
    }
}

// ---------------------------------------------------------------------------
// launch
// ---------------------------------------------------------------------------
extern "C" void kernel_launch(void* const* d_in, const int* in_sizes, int n_in,
                              void* d_out, int out_size)
{
    const float* x   = (const float*)d_in[0];
    const float* h0  = (const float*)d_in[1];
    const float* Wz  = (const float*)d_in[2];
    const float* Wzb = (const float*)d_in[3];
    const float* Uz  = (const float*)d_in[4];
    const float* Uzb = (const float*)d_in[5];
    const float* Wr  = (const float*)d_in[6];
    const float* Wrb = (const float*)d_in[7];
    const float* Ur  = (const float*)d_in[8];
    const float* Urb = (const float*)d_in[9];
    const float* Wh  = (const float*)d_in[10];
    const float* Whb = (const float*)d_in[11];
    const float* Uh  = (const float*)d_in[12];
    const float* Uhb = (const float*)d_in[13];
    float* out = (float*)d_out;

    // pre-GEMM: grid (M/128, N/128) = (512, 12)
    dim3 ggrid(512, 12);
    pregemm_kernel<<<ggrid, 256>>>(x, Wz, Wzb, Wr, Wrb, Wh, Whb);

    // recurrence: 128 persistent CTAs, 154 KB dynamic smem
    const int smem_bytes = (6144 + 64 * HS_PITCH + 256) * (int)sizeof(float);
    static int attr_set = 0;
    if (!attr_set) {
        cudaFuncSetAttribute(gru_rec_kernel,
                             cudaFuncAttributeMaxDynamicSharedMemorySize, smem_bytes);
        attr_set = 1;
    }
    gru_rec_kernel<<<NB_REC, 256, smem_bytes>>>(h0, Uz, Uzb, Ur, Urb, Uh, Uhb, out);
}

// round 2
// speedup vs baseline: 1.4454x; 1.4454x over previous
#include <cuda_runtime.h>
#include <math.h>

// ---------------------------------------------------------------------------
// GRU: S=1024, B=64, I=512, H=512, fp32
// Phase 1: pregemm  -> g_xg[s][gate][hc][b] = x[s,b,:] . W_g[hc,:] + b_g[hc]
// Phase 2: persistent recurrence kernel, 128 CTAs x 512 thr, split-K(2),
//          hard-spin grid barrier.
// ---------------------------------------------------------------------------

#define S_LEN 1024
#define B_DIM 64
#define I_DIM 512
#define H_DIM 512
#define NB_REC 128          // recurrence grid size (must be <= #SMs)

// scratch: (S, 3, H, B) fp32 = 402 MB
__device__ float g_xg[(size_t)S_LEN * 3 * H_DIM * B_DIM];
// r*h exchange buffer, (B,H) row-major
__device__ float g_rh[B_DIM * H_DIM];
// grid barrier state
__device__ unsigned g_cnt = 0;
__device__ unsigned g_gen = 0;

// ---------------------------------------------------------------------------
// Phase 1: SGEMM  C[m][n] = sum_k A[m][k]*W[n][k] + bias[n]
//   A = x, M = 65536 (m = s*64+b), N = 1536 (n = g*512+hc), K = 512
//   BM=128, BN=128, BK=8, 256 threads, 8x8 thread tile.
//   Store layout: g_xg[((s*3+g)*512+hc)*64 + b]  (coalesced over b)
// ---------------------------------------------------------------------------
__global__ __launch_bounds__(256) void pregemm_kernel(
    const float* __restrict__ x,
    const float* __restrict__ Wz, const float* __restrict__ Wzb,
    const float* __restrict__ Wr, const float* __restrict__ Wrb,
    const float* __restrict__ Wh, const float* __restrict__ Whb)
{
    __shared__ float As[8][132];
    __shared__ float Bs[8][132];

    const int tid = threadIdx.x;
    const int m0 = blockIdx.x * 128;
    const int n0 = blockIdx.y * 128;
    const int g  = n0 >> 9;          // gate (tile never crosses gate boundary)
    const int r0 = n0 & 511;         // row offset within gate weight matrix

    const float* W  = (g == 0) ? Wz  : (g == 1) ? Wr  : Wh;
    const float* Wb = (g == 0) ? Wzb : (g == 1) ? Wrb : Whb;

    const int lm  = tid >> 1;        // 0..127
    const int lk4 = (tid & 1) << 2;  // 0 or 4
    const float* Aptr = x + (size_t)(m0 + lm) * I_DIM + lk4;
    const float* Bptr = W + (size_t)(r0 + lm) * I_DIM + lk4;

    const int tm = tid & 15;         // m-direction (lanes over m -> coalesced C)
    const int tn = tid >> 4;         // n-direction

    float acc[8][8];
    #pragma unroll
    for (int i = 0; i < 8; i++)
        #pragma unroll
        for (int j = 0; j < 8; j++) acc[i][j] = 0.0f;

    for (int k0 = 0; k0 < I_DIM; k0 += 8) {
        float4 av = *(const float4*)(Aptr + k0);
        float4 bv = *(const float4*)(Bptr + k0);
        __syncthreads();
        As[lk4 + 0][lm] = av.x; As[lk4 + 1][lm] = av.y;
        As[lk4 + 2][lm] = av.z; As[lk4 + 3][lm] = av.w;
        Bs[lk4 + 0][lm] = bv.x; Bs[lk4 + 1][lm] = bv.y;
        Bs[lk4 + 2][lm] = bv.z; Bs[lk4 + 3][lm] = bv.w;
        __syncthreads();
        #pragma unroll
        for (int k = 0; k < 8; k++) {
            float a[8], bb[8];
            *(float4*)(a)     = *(const float4*)(&As[k][tm * 8]);
            *(float4*)(a + 4) = *(const float4*)(&As[k][tm * 8 + 4]);
            *(float4*)(bb)     = *(const float4*)(&Bs[k][tn * 8]);
            *(float4*)(bb + 4) = *(const float4*)(&Bs[k][tn * 8 + 4]);
            #pragma unroll
            for (int i = 0; i < 8; i++)
                #pragma unroll
                for (int j = 0; j < 8; j++)
                    acc[i][j] = fmaf(a[i], bb[j], acc[i][j]);
        }
    }

    const int gm = m0 + tm * 8;      // 8 consecutive m: same s, b..b+7
    const int s  = gm >> 6;
    const int b  = gm & 63;
    #pragma unroll
    for (int j = 0; j < 8; j++) {
        const int n = n0 + tn * 8 + j;
        const float bias = Wb[r0 + tn * 8 + j];
        float* op = g_xg + (size_t)s * (3 * H_DIM * B_DIM) + (size_t)n * B_DIM + b;
        float4 v0 = make_float4(acc[0][j] + bias, acc[1][j] + bias,
                                acc[2][j] + bias, acc[3][j] + bias);
        float4 v1 = make_float4(acc[4][j] + bias, acc[5][j] + bias,
                                acc[6][j] + bias, acc[7][j] + bias);
        *(float4*)(op)     = v0;
        *(float4*)(op + 4) = v1;
    }
}

// ---------------------------------------------------------------------------
// grid-wide barrier: hard spin (no nanosleep -> sub-us wakeup)
// ---------------------------------------------------------------------------
__device__ __forceinline__ void grid_sync()
{
    __syncthreads();
    if (threadIdx.x == 0) {
        __threadfence();
        volatile unsigned* genp = &g_gen;
        unsigned gen = *genp;
        unsigned arrived = atomicAdd(&g_cnt, 1u);
        if (arrived == NB_REC - 1u) {
            atomicExch(&g_cnt, 0u);
            __threadfence();
            atomicAdd(&g_gen, 1u);
        } else {
            while (*genp == gen) { }
        }
        __threadfence();
    }
    __syncthreads();
}

// ---------------------------------------------------------------------------
// Phase 2: persistent recurrence.
//   128 CTAs x 512 threads. CTA bx owns hcols [bx*4, bx*4+4).
//   Thread: g2 = tid>>8 (k-half), b = tid&63, hcl = (tid>>6)&3.
//   Each thread computes partial dot over 256 k; group1 deposits partials
//   in smem; group0 combines, applies activations, writes results.
//   smem: Uz/Ur/Uh rows (24KB, persistent) + h/rh stage [64][516] (129KB)
//         + partials pz/pr/ph [256]x3 + hout[256]
// ---------------------------------------------------------------------------
#define HS_PITCH 516   // 512 + 4 pad -> conflict-free LDS.128 with lanes over b

__global__ __launch_bounds__(512) void gru_rec_kernel(
    const float* __restrict__ h0,
    const float* __restrict__ Uz, const float* __restrict__ Uzb,
    const float* __restrict__ Ur, const float* __restrict__ Urb,
    const float* __restrict__ Uh, const float* __restrict__ Uhb,
    float* __restrict__ out)
{
    extern __shared__ float sm[];
    float* Uzs  = sm;                            // [4][512]
    float* Urs  = sm + 2048;                     // [4][512]
    float* Uhs  = sm + 4096;                     // [4][512]
    float* hs   = sm + 6144;                     // [64][516]
    float* pz   = sm + 6144 + 64 * HS_PITCH;     // [256]
    float* pr   = pz + 256;                      // [256]
    float* ph   = pr + 256;                      // [256]
    float* hout = ph + 256;                      // [256] = [64][4]

    const int tid = threadIdx.x;
    const int g2  = tid >> 8;                    // k-half: 0 or 1
    const int rr  = tid & 255;                   // (b, hcl) index
    const int b   = rr & 63;
    const int hcl = rr >> 6;                     // 0..3
    const int hc  = blockIdx.x * 4 + hcl;        // global h column
    const int kofs = g2 << 8;                    // 0 or 256

    // load this CTA's U rows into smem (persistent across all steps)
    for (int i = tid; i < 4 * 512; i += 512) {
        const int r = i >> 9, c = i & 511;
        const size_t widx = (size_t)(blockIdx.x * 4 + r) * H_DIM + c;
        Uzs[i] = Uz[widx];
        Urs[i] = Ur[widx];
        Uhs[i] = Uh[widx];
    }
    const float bzv = Uzb[hc];
    const float brv = Urb[hc];
    const float bhv = Uhb[hc];

    const float* hprev = h0;   // (B,H) row-major

    for (int t = 0; t < S_LEN; t++) {
        // prefetch x-projection operands (independent of staging/sync)
        const size_t xbase = (size_t)t * (3 * H_DIM * B_DIM) + (size_t)hc * B_DIM + b;
        float xz = 0.f, xr = 0.f, xh = 0.f;
        if (g2 == 0) {
            xz = g_xg[xbase];
            xr = g_xg[xbase + (size_t)H_DIM * B_DIM];
            xh = g_xg[xbase + (size_t)2 * H_DIM * B_DIM];
        }

        // ---- stage h_prev into smem (coalesced float4) ----
        __syncthreads();
        for (int i = tid; i < 64 * 128; i += 512) {
            const int bb = i >> 7, k4 = i & 127;
            *(float4*)(hs + bb * HS_PITCH + k4 * 4) =
                *(const float4*)(hprev + bb * H_DIM + k4 * 4);
        }
        __syncthreads();

        // ---- phase 1: z and r partial dots over this thread's k-half ----
        float az = 0.f, ar = 0.f;
        {
            const float* hrow = hs + b * HS_PITCH + kofs;
            const float* uzr  = Uzs + hcl * 512 + kofs;
            const float* urr  = Urs + hcl * 512 + kofs;
            #pragma unroll 4
            for (int k4 = 0; k4 < 64; k4++) {
                float4 hv = *(const float4*)(hrow + k4 * 4);
                float4 uz = *(const float4*)(uzr + k4 * 4);
                float4 ur = *(const float4*)(urr + k4 * 4);
                az = fmaf(hv.x, uz.x, az); az = fmaf(hv.y, uz.y, az);
                az = fmaf(hv.z, uz.z, az); az = fmaf(hv.w, uz.w, az);
                ar = fmaf(hv.x, ur.x, ar); ar = fmaf(hv.y, ur.y, ar);
                ar = fmaf(hv.z, ur.z, ar); ar = fmaf(hv.w, ur.w, ar);
            }
        }
        if (g2 == 1) { pz[rr] = az; pr[rr] = ar; }
        __syncthreads();

        float z = 0.f, hown = 0.f;
        if (g2 == 0) {
            az += pz[rr] + bzv + xz;
            ar += pr[rr] + brv + xr;
            z = 1.0f / (1.0f + __expf(-az));
            const float r = 1.0f / (1.0f + __expf(-ar));
            hown = hs[b * HS_PITCH + hc];
            hout[b * 4 + hcl] = r * hown;   // gather r*h for coalesced write
        }
        __syncthreads();
        if (tid < 64) {                      // coalesced float4 store of r*h
            float4 v = *(const float4*)(hout + tid * 4);
            *(float4*)(g_rh + tid * H_DIM + blockIdx.x * 4) = v;
        }

        grid_sync();   // all r*h written globally

        // ---- stage r*h into smem ----
        for (int i = tid; i < 64 * 128; i += 512) {
            const int bb = i >> 7, k4 = i & 127;
            *(float4*)(hs + bb * HS_PITCH + k4 * 4) =
                *(const float4*)(g_rh + bb * H_DIM + k4 * 4);
        }
        __syncthreads();

        // ---- phase 2: candidate partial dot ----
        float ah = 0.f;
        {
            const float* rrow = hs + b * HS_PITCH + kofs;
            const float* uhr  = Uhs + hcl * 512 + kofs;
            #pragma unroll 4
            for (int k4 = 0; k4 < 64; k4++) {
                float4 rv = *(const float4*)(rrow + k4 * 4);
                float4 uh = *(const float4*)(uhr + k4 * 4);
                ah = fmaf(rv.x, uh.x, ah); ah = fmaf(rv.y, uh.y, ah);
                ah = fmaf(rv.z, uh.z, ah); ah = fmaf(rv.w, uh.w, ah);
            }
        }
        if (g2 == 1) { ph[rr] = ah; }
        __syncthreads();
        if (g2 == 0) {
            ah += ph[rr] + bhv + xh;
            const float htld = tanhf(ah);
            hout[b * 4 + hcl] = (1.0f - z) * hown + z * htld;
        }
        __syncthreads();

        // coalesced write of this CTA's 4 columns for all 64 b
        if (tid < 64) {
            float4 v = *(const float4*)(hout + tid * 4);
            *(float4*)(out + (size_t)t * (B_DIM * H_DIM) + tid * H_DIM + blockIdx.x * 4) = v;
        }

        grid_sync();   // h_t fully written -> next step may stage it
        hprev = out + (size_t)t * (B_DIM * H_DIM);
    }

    // hx = h_{S-1}
    if (tid < 64) {
        float4 v = *(const float4*)(hout + tid * 4);
        *(float4*)(out + (size_t)S_LEN * (B_DIM * H_DIM) + tid * H_DIM + blockIdx.x * 4) = v;
    }
}

// ---------------------------------------------------------------------------
// launch
// ---------------------------------------------------------------------------
extern "C" void kernel_launch(void* const* d_in, const int* in_sizes, int n_in,
                              void* d_out, int out_size)
{
    const float* x   = (const float*)d_in[0];
    const float* h0  = (const float*)d_in[1];
    const float* Wz  = (const float*)d_in[2];
    const float* Wzb = (const float*)d_in[3];
    const float* Uz  = (const float*)d_in[4];
    const float* Uzb = (const float*)d_in[5];
    const float* Wr  = (const float*)d_in[6];
    const float* Wrb = (const float*)d_in[7];
    const float* Ur  = (const float*)d_in[8];
    const float* Urb = (const float*)d_in[9];
    const float* Wh  = (const float*)d_in[10];
    const float* Whb = (const float*)d_in[11];
    const float* Uh  = (const float*)d_in[12];
    const float* Uhb = (const float*)d_in[13];
    float* out = (float*)d_out;

    // pre-GEMM: grid (M/128, N/128) = (512, 12)
    dim3 ggrid(512, 12);
    pregemm_kernel<<<ggrid, 256>>>(x, Wz, Wzb, Wr, Wrb, Wh, Whb);

    // recurrence: 128 persistent CTAs, ~161 KB dynamic smem
    const int smem_bytes = (6144 + 64 * HS_PITCH + 4 * 256) * (int)sizeof(float);
    static int attr_set = 0;
    if (!attr_set) {
        cudaFuncSetAttribute(gru_rec_kernel,
                             cudaFuncAttributeMaxDynamicSharedMemorySize, smem_bytes);
        attr_set = 1;
    }
    gru_rec_kernel<<<NB_REC, 512, smem_bytes>>>(h0, Uz, Uzb, Ur, Urb, Uh, Uhb, out);
}